// round 16
// baseline (speedup 1.0000x reference)
#include <cuda_runtime.h>
#include <cuda_fp16.h>
#include <cstdint>
#include <math.h>

#define BB 2
#define S_IMG 1024
#define S_TXT 512
#define SEQ 1536
#define DIM 3072
#define HEADS 24
#define HD 128
#define EPSF 1e-6f
#define SCALEF 0.08838834764831845f

// Scratch (device globals -- no allocation allowed)
__device__ __half g_Whi[8 * DIM * DIM];
__device__ __half g_Xhi[BB * SEQ * DIM];
__device__ __half g_Qhi[BB * SEQ * DIM];
__device__ __half g_Khi[BB * SEQ * DIM];
__device__ __half g_Vhi[BB * SEQ * DIM];

// ===========================================================================
// helpers
// ===========================================================================
__device__ __forceinline__ uint32_t smem_u32(const void* p) {
    uint32_t a;
    asm("{ .reg .u64 t; cvta.to.shared.u64 t, %1; cvt.u32.u64 %0, t; }"
        : "=r"(a) : "l"(p));
    return a;
}
#define LDM4(r, a) \
    asm volatile("ldmatrix.sync.aligned.m8n8.x4.shared.b16 {%0,%1,%2,%3}, [%4];" \
        : "=r"((r)[0]), "=r"((r)[1]), "=r"((r)[2]), "=r"((r)[3]) : "r"(a))
#define LDM4T(r, a) \
    asm volatile("ldmatrix.sync.aligned.m8n8.x4.trans.shared.b16 {%0,%1,%2,%3}, [%4];" \
        : "=r"((r)[0]), "=r"((r)[1]), "=r"((r)[2]), "=r"((r)[3]) : "r"(a))
#define MMA_F16(d, a, b0, b1) \
    asm volatile("mma.sync.aligned.m16n8k16.row.col.f32.f16.f16.f32 " \
        "{%0,%1,%2,%3}, {%4,%5,%6,%7}, {%8,%9}, {%0,%1,%2,%3};" \
        : "+f"((d)[0]), "+f"((d)[1]), "+f"((d)[2]), "+f"((d)[3]) \
        : "r"((a)[0]), "r"((a)[1]), "r"((a)[2]), "r"((a)[3]), "r"(b0), "r"(b1))
#define CPA16(dst, src) \
    asm volatile("cp.async.cg.shared.global [%0], [%1], 16;" :: "r"(dst), "l"(src))
#define CP_COMMIT() asm volatile("cp.async.commit_group;" ::: "memory")
#define CP_WAIT(n)  asm volatile("cp.async.wait_group %0;" :: "n"(n) : "memory")

__device__ __forceinline__ uint32_t pack_h2(float a, float b) {
    __half2 h = __floats2half2_rn(a, b);
    return *(uint32_t*)&h;
}

// ---------------------------------------------------------------------------
// conversion kernels
// ---------------------------------------------------------------------------
__global__ void __launch_bounds__(256) conv_w8_kernel(
    const float4* __restrict__ w0, const float4* __restrict__ w1,
    const float4* __restrict__ w2, const float4* __restrict__ w3,
    const float4* __restrict__ w4, const float4* __restrict__ w5,
    const float4* __restrict__ w6, const float4* __restrict__ w7,
    uint2* __restrict__ hi, int n4)
{
    int i = blockIdx.x * 256 + threadIdx.x;
    int z = blockIdx.y;
    if (i < n4) {
        const float4* src = (z == 0) ? w0 : (z == 1) ? w1 : (z == 2) ? w2 : (z == 3) ? w3
                          : (z == 4) ? w4 : (z == 5) ? w5 : (z == 6) ? w6 : w7;
        float4 v = src[i];
        uint2 ph;
        ph.x = pack_h2(v.x, v.y);
        ph.y = pack_h2(v.z, v.w);
        hi[(size_t)z * n4 + i] = ph;
    }
}

__global__ void __launch_bounds__(256) conv_hi_kernel(
    const float4* __restrict__ src, uint2* __restrict__ hi, int rpb, int dst_off)
{
    int i = blockIdx.x * 256 + threadIdx.x;
    int n4 = BB * rpb * (DIM / 4);
    if (i < n4) {
        int q = i % (DIM / 4);
        int row = i / (DIM / 4);
        int b = row / rpb, s = row % rpb;
        float4 v = src[i];
        uint2 ph;
        ph.x = pack_h2(v.x, v.y);
        ph.y = pack_h2(v.z, v.w);
        hi[(b * SEQ + dst_off + s) * (DIM / 4) + q] = ph;
    }
}

// ===========================================================================
// fp16 1-pass GEMM, tile 128x128, 128 threads = 4 warps each owning 64x64.
// KC=32, 6-stage cp.async, ONE barrier per 2 chunks (pair pipelining).
// Fused epilogues (hi-only outputs) as in R14.
// ===========================================================================
#define KC 32
#define CHUNKS (DIM / KC)                  // 96
#define A_ST2 80
#define B_ST2 272
#define A_TILE_B (128 * A_ST2)              // 10240
#define B_TILE_B (32 * B_ST2)               // 8704
#define OFF_BHI A_TILE_B
#define STAGE_B (A_TILE_B + B_TILE_B)       // 18944
#define NSTAGE 6
#define GEMM_SMEM_BYTES (NSTAGE * STAGE_B)  // 113664 (2 CTA/SM: 227328 <= 228K)

__global__ void __launch_bounds__(128, 2) mma_gemm_kernel(
    int mode,
    const __half* __restrict__ Xg,
    const __half* __restrict__ Whi_base,
    const float* bq, const float* bk, const float* bv,
    const float* bqc, const float* bkc, const float* bvc,
    const float* b_out, const float* b_add,
    const float* g_q, const float* g_k, const float* g_qc, const float* g_kc,
    const float* __restrict__ cosb, const float* __restrict__ sinb,
    __half* Qhi, __half* Khi, __half* Vhi,
    float* out)
{
    extern __shared__ __align__(128) char smem[];
    const uint32_t sbase = smem_u32(smem);
    const int tid = threadIdx.x;
    const int wid = tid >> 5, lane = tid & 31;
    const int warp_m = wid >> 1;
    const int warp_n = wid & 1;
    const int z = blockIdx.z;

    const int row0 = blockIdx.y * 128;
    const int col0 = blockIdx.x * 128;
    const int b  = row0 / SEQ;
    const int sj = row0 % SEQ;
    const bool txt = (sj < S_TXT);

    int widx;
    const float* bias;
    __half* Hz = nullptr;
    const float* Gz = nullptr;
    float* C = nullptr;
    if (mode == 0) {
        widx = txt ? (3 + z) : z;
        bias = (z == 0) ? (txt ? bqc : bq) : (z == 1) ? (txt ? bkc : bk) : (txt ? bvc : bv);
        Hz = (z == 0) ? Qhi : (z == 1) ? Khi : Vhi;
        Gz = (z == 0) ? (txt ? g_qc : g_q) : (z == 1) ? (txt ? g_kc : g_k) : nullptr;
    } else {
        widx = txt ? 7 : 6;
        bias = txt ? b_add : b_out;
        size_t crow = txt ? (size_t)(b * S_TXT + sj)
                          : (size_t)(BB * S_TXT + b * S_IMG + (sj - S_TXT));
        C = out + crow * DIM;
    }
    const __half* Whi = Whi_base + (size_t)widx * DIM * DIM;
    const __half* Ahi = Xg + (size_t)row0 * DIM;

#define ISSUE(c) do { \
    const int k0 = (c) * KC; \
    const uint32_t stb = sbase + ((c) % NSTAGE) * STAGE_B; \
    _Pragma("unroll") \
    for (int i = 0; i < 4; i++) { \
        int f = tid + i * 128; \
        uint32_t d = stb + (uint32_t)(f >> 2) * A_ST2 + (f & 3) * 16; \
        size_t so = (size_t)(f >> 2) * DIM + k0 + ((f & 3) << 3); \
        CPA16(d, (const void*)(Ahi + so)); \
        uint32_t db = stb + OFF_BHI + (uint32_t)(f >> 4) * B_ST2 + (f & 15) * 16; \
        size_t sb2 = (size_t)(k0 + (f >> 4)) * DIM + col0 + ((f & 15) << 3); \
        CPA16(db, (const void*)(Whi + sb2)); \
    } \
    CP_COMMIT(); \
} while (0)

    float acc[4][8][4];
#pragma unroll
    for (int i = 0; i < 4; i++)
#pragma unroll
        for (int j = 0; j < 8; j++)
#pragma unroll
            for (int k = 0; k < 4; k++) acc[i][j][k] = 0.f;

    const uint32_t a_row = (uint32_t)(warp_m * 64 + (lane & 15));
    const uint32_t a_sel = (uint32_t)((lane >> 4) * 16);
    const uint32_t b_row = (uint32_t)(lane & 15);
    const uint32_t b_sel = (uint32_t)(warp_n * 128 + ((lane >> 4) * 16));

#define COMPUTE(sidx) do { \
    const uint32_t sb = sbase + (sidx) * STAGE_B; \
    _Pragma("unroll") \
    for (int ks = 0; ks < 2; ks++) { \
        uint32_t ah[4][4]; \
        _Pragma("unroll") \
        for (int mt = 0; mt < 4; mt++) { \
            uint32_t ad = sb + (a_row + mt * 16) * A_ST2 + ks * 32 + a_sel; \
            LDM4(ah[mt], ad); \
        } \
        _Pragma("unroll") \
        for (int ng = 0; ng < 4; ng++) { \
            uint32_t bh[4]; \
            uint32_t bd = sb + OFF_BHI + (ks * 16 + b_row) * B_ST2 + b_sel + ng * 32; \
            LDM4T(bh, bd); \
            _Pragma("unroll") \
            for (int mt = 0; mt < 4; mt++) { \
                MMA_F16(acc[mt][ng * 2 + 0], ah[mt], bh[0], bh[1]); \
                MMA_F16(acc[mt][ng * 2 + 1], ah[mt], bh[2], bh[3]); \
            } \
        } \
    } \
} while (0)

    // pair-chunk pipeline: one barrier per 2 chunks, 6 buffers in flight
    ISSUE(0); ISSUE(1); ISSUE(2); ISSUE(3);
    for (int c = 0; c < CHUNKS; c += 2) {
        if (c < CHUNKS - 2) { CP_WAIT(2); } else { CP_WAIT(0); }
        __syncthreads();
        if (c + 4 < CHUNKS) ISSUE(c + 4);
        if (c + 5 < CHUNKS) ISSUE(c + 5);
        COMPUTE(c % NSTAGE);
        COMPUTE((c + 1) % NSTAGE);
    }

    // ---------------- epilogue ----------------
    const int m_base = warp_m * 64;
    const int n_loc  = warp_n * 64;

#pragma unroll
    for (int mt = 0; mt < 4; mt++)
#pragma unroll
        for (int nt = 0; nt < 8; nt++) {
            int cc = col0 + n_loc + nt * 8 + ((lane & 3) << 1);
            float b0 = bias[cc], b1 = bias[cc + 1];
            acc[mt][nt][0] += b0; acc[mt][nt][1] += b1;
            acc[mt][nt][2] += b0; acc[mt][nt][3] += b1;
        }

    if (mode == 1) {
#pragma unroll
        for (int mt = 0; mt < 4; mt++)
#pragma unroll
            for (int nt = 0; nt < 8; nt++) {
                int r  = m_base + mt * 16 + (lane >> 2);
                int cc = col0 + n_loc + nt * 8 + ((lane & 3) << 1);
                *(float2*)(C + (size_t)r * DIM + cc) =
                    make_float2(acc[mt][nt][0], acc[mt][nt][1]);
                *(float2*)(C + (size_t)(r + 8) * DIM + cc) =
                    make_float2(acc[mt][nt][2], acc[mt][nt][3]);
            }
    } else if (Gz == nullptr) {
        // V path: fp16 hi
#pragma unroll
        for (int mt = 0; mt < 4; mt++)
#pragma unroll
            for (int nt = 0; nt < 8; nt++) {
                int r  = m_base + mt * 16 + (lane >> 2);
                int cc = col0 + n_loc + nt * 8 + ((lane & 3) << 1);
                *(uint32_t*)(Hz + (size_t)(row0 + r) * DIM + cc) =
                    pack_h2(acc[mt][nt][0], acc[mt][nt][1]);
                *(uint32_t*)(Hz + (size_t)(row0 + r + 8) * DIM + cc) =
                    pack_h2(acc[mt][nt][2], acc[mt][nt][3]);
            }
    } else {
        // Q/K path: RMS-norm over the 128-col head + RoPE, fp16 hi out
        __syncthreads();
        float* red = (float*)smem;           // [128][2]
        float ss[4][2];
#pragma unroll
        for (int mt = 0; mt < 4; mt++) {
            float p0 = 0.f, p1 = 0.f;
#pragma unroll
            for (int nt = 0; nt < 8; nt++) {
                p0 += acc[mt][nt][0] * acc[mt][nt][0] + acc[mt][nt][1] * acc[mt][nt][1];
                p1 += acc[mt][nt][2] * acc[mt][nt][2] + acc[mt][nt][3] * acc[mt][nt][3];
            }
            p0 += __shfl_xor_sync(0xffffffffu, p0, 1);
            p0 += __shfl_xor_sync(0xffffffffu, p0, 2);
            p1 += __shfl_xor_sync(0xffffffffu, p1, 1);
            p1 += __shfl_xor_sync(0xffffffffu, p1, 2);
            ss[mt][0] = p0; ss[mt][1] = p1;
        }
        if ((lane & 3) == 0) {
#pragma unroll
            for (int mt = 0; mt < 4; mt++) {
                int rl = m_base + mt * 16 + (lane >> 2);
                red[rl * 2 + warp_n] = ss[mt][0];
                red[(rl + 8) * 2 + warp_n] = ss[mt][1];
            }
        }
        __syncthreads();
#pragma unroll
        for (int mt = 0; mt < 4; mt++) {
            int rl = m_base + mt * 16 + (lane >> 2);
            float sm0 = red[rl * 2 + 0] + red[rl * 2 + 1];
            float sm1 = red[(rl + 8) * 2 + 0] + red[(rl + 8) * 2 + 1];
            float scl0 = rsqrtf(sm0 * (1.0f / HD) + EPSF);
            float scl1 = rsqrtf(sm1 * (1.0f / HD) + EPSF);
            int sp0 = sj + rl;
            int sp1 = sp0 + 8;
#pragma unroll
            for (int nt = 0; nt < 8; nt++) {
                int d  = n_loc + nt * 8 + ((lane & 3) << 1);
                int cc = col0 + d;
                float gd0 = Gz[d], gd1 = Gz[d + 1];
                float c0 = cosb[sp0 * (HD / 2) + (d >> 1)];
                float n0 = sinb[sp0 * (HD / 2) + (d >> 1)];
                float c1 = cosb[sp1 * (HD / 2) + (d >> 1)];
                float n1 = sinb[sp1 * (HD / 2) + (d >> 1)];
                float x0 = acc[mt][nt][0] * scl0 * gd0;
                float x1 = acc[mt][nt][1] * scl0 * gd1;
                float y0 = acc[mt][nt][2] * scl1 * gd0;
                float y1 = acc[mt][nt][3] * scl1 * gd1;
                *(uint32_t*)(Hz + (size_t)(row0 + rl) * DIM + cc) =
                    pack_h2(x0 * c0 - x1 * n0, x0 * n0 + x1 * c0);
                *(uint32_t*)(Hz + (size_t)(row0 + rl + 8) * DIM + cc) =
                    pack_h2(y0 * c1 - y1 * n1, y0 * n1 + y1 * c1);
            }
        }
    }
#undef ISSUE
#undef COMPUTE
}

// ===========================================================================
// Flash attention via mma.sync, pure fp16. BM=128, BN=32, HD=128.
// 6-stage K/V pipeline, ONE barrier per 2 key-tiles (pair pipelining).
// ===========================================================================
#define FROW_B 272
#define FK_HI 0
#define FV_HI (32 * FROW_B)
#define FSTAGE_B (2 * 32 * FROW_B)          // 17408
#define FNSTAGE 6
#define FLASH_SMEM_BYTES (FNSTAGE * FSTAGE_B)   // 104448 (>= Q staging 34816)
#define FITERS (SEQ / 32)                    // 48

__global__ void __launch_bounds__(256) flash_mma_kernel(
    const __half* __restrict__ Qhi_g,
    const __half* __restrict__ Khi_g,
    const __half* __restrict__ Vhi_g,
    __half* __restrict__ Ohi)
{
    extern __shared__ __align__(128) char smem[];
    const uint32_t sbase = smem_u32(smem);
    const int tid = threadIdx.x;
    const int wq = tid >> 5, lane = tid & 31;
    const int q0 = blockIdx.x * 128;
    const int bh = blockIdx.y;
    const int b = bh / HEADS, h = bh % HEADS;
    const size_t hoff = (size_t)h * HD;

    // stage Q (hi only), pull into registers
    {
#pragma unroll
        for (int i = 0; i < 8; i++) {
            int f = tid + i * 256;
            int r = f >> 4, c = f & 15;
            uint32_t d = sbase + (uint32_t)r * FROW_B + c * 16;
            size_t so = (size_t)(b * SEQ + q0 + r) * DIM + hoff + c * 8;
            CPA16(d, (const void*)(Qhi_g + so));
        }
        CP_COMMIT();
        CP_WAIT(0);
        __syncthreads();
    }
    uint32_t qh[8][4];
    {
        const uint32_t qrow = (uint32_t)(wq * 16 + (lane & 15));
        const uint32_t qc8  = (uint32_t)((lane >> 4) * 16);
#pragma unroll
        for (int ks = 0; ks < 8; ks++) {
            uint32_t ad = sbase + qrow * FROW_B + ks * 32 + qc8;
            LDM4(qh[ks], ad);
        }
    }
    __syncthreads();

#define FISSUE(kt) do { \
    const int k0 = (kt) * 32; \
    const uint32_t stb = sbase + ((kt) % FNSTAGE) * FSTAGE_B; \
    _Pragma("unroll") \
    for (int i = 0; i < 2; i++) { \
        int f = tid + i * 256; \
        int r = f >> 4, c = f & 15; \
        uint32_t d = stb + (uint32_t)r * FROW_B + c * 16; \
        size_t so = (size_t)(b * SEQ + k0 + r) * DIM + hoff + c * 8; \
        CPA16(d + FK_HI, (const void*)(Khi_g + so)); \
        CPA16(d + FV_HI, (const void*)(Vhi_g + so)); \
    } \
    CP_COMMIT(); \
} while (0)

    float acc[16][4];
#pragma unroll
    for (int i = 0; i < 16; i++)
#pragma unroll
        for (int j = 0; j < 4; j++) acc[i][j] = 0.f;
    float m0 = -1e30f, m1 = -1e30f, l0 = 0.f, l1 = 0.f;

    const uint32_t krow = (uint32_t)(lane & 15);
    const uint32_t kc8  = (uint32_t)((lane >> 4) * 16);

    // per-key-tile body (warp-local; no CTA sync inside)
#define FBODY(kt) do { \
    const uint32_t stb = sbase + ((kt) % FNSTAGE) * FSTAGE_B; \
    float s[4][4]; \
    _Pragma("unroll") \
    for (int i = 0; i < 4; i++) \
        _Pragma("unroll") \
        for (int j = 0; j < 4; j++) s[i][j] = 0.f; \
    _Pragma("unroll") \
    for (int ks = 0; ks < 8; ks++) { \
        _Pragma("unroll") \
        for (int half = 0; half < 2; half++) { \
            uint32_t kbh[4]; \
            uint32_t kd = stb + FK_HI + (half * 16 + krow) * FROW_B + ks * 32 + kc8; \
            LDM4(kbh, kd); \
            MMA_F16(s[2 * half + 0], qh[ks], kbh[0], kbh[2]); \
            MMA_F16(s[2 * half + 1], qh[ks], kbh[1], kbh[3]); \
        } \
    } \
    _Pragma("unroll") \
    for (int i = 0; i < 4; i++) \
        _Pragma("unroll") \
        for (int j = 0; j < 4; j++) s[i][j] *= SCALEF; \
    float mx0 = fmaxf(fmaxf(s[0][0], s[0][1]), fmaxf(s[1][0], s[1][1])); \
    mx0 = fmaxf(mx0, fmaxf(fmaxf(s[2][0], s[2][1]), fmaxf(s[3][0], s[3][1]))); \
    float mx1 = fmaxf(fmaxf(s[0][2], s[0][3]), fmaxf(s[1][2], s[1][3])); \
    mx1 = fmaxf(mx1, fmaxf(fmaxf(s[2][2], s[2][3]), fmaxf(s[3][2], s[3][3]))); \
    _Pragma("unroll") \
    for (int o = 1; o <= 2; o <<= 1) { \
        mx0 = fmaxf(mx0, __shfl_xor_sync(0xffffffffu, mx0, o)); \
        mx1 = fmaxf(mx1, __shfl_xor_sync(0xffffffffu, mx1, o)); \
    } \
    float mn0 = fmaxf(m0, mx0), mn1 = fmaxf(m1, mx1); \
    float f0 = __expf(m0 - mn0), f1 = __expf(m1 - mn1); \
    m0 = mn0; m1 = mn1; \
    float rs0 = 0.f, rs1 = 0.f; \
    _Pragma("unroll") \
    for (int nt = 0; nt < 4; nt++) { \
        s[nt][0] = __expf(s[nt][0] - mn0); \
        s[nt][1] = __expf(s[nt][1] - mn0); \
        s[nt][2] = __expf(s[nt][2] - mn1); \
        s[nt][3] = __expf(s[nt][3] - mn1); \
        rs0 += s[nt][0] + s[nt][1]; \
        rs1 += s[nt][2] + s[nt][3]; \
    } \
    _Pragma("unroll") \
    for (int o = 1; o <= 2; o <<= 1) { \
        rs0 += __shfl_xor_sync(0xffffffffu, rs0, o); \
        rs1 += __shfl_xor_sync(0xffffffffu, rs1, o); \
    } \
    l0 = l0 * f0 + rs0; \
    l1 = l1 * f1 + rs1; \
    _Pragma("unroll") \
    for (int i = 0; i < 16; i++) { \
        acc[i][0] *= f0; acc[i][1] *= f0; \
        acc[i][2] *= f1; acc[i][3] *= f1; \
    } \
    uint32_t ph[2][4]; \
    _Pragma("unroll") \
    for (int k2 = 0; k2 < 2; k2++) { \
        ph[k2][0] = pack_h2(s[2 * k2][0],     s[2 * k2][1]); \
        ph[k2][1] = pack_h2(s[2 * k2][2],     s[2 * k2][3]); \
        ph[k2][2] = pack_h2(s[2 * k2 + 1][0], s[2 * k2 + 1][1]); \
        ph[k2][3] = pack_h2(s[2 * k2 + 1][2], s[2 * k2 + 1][3]); \
    } \
    _Pragma("unroll") \
    for (int ng = 0; ng < 8; ng++) { \
        _Pragma("unroll") \
        for (int k2 = 0; k2 < 2; k2++) { \
            uint32_t vbh[4]; \
            uint32_t vd = stb + FV_HI + (k2 * 16 + krow) * FROW_B + ng * 32 + kc8; \
            LDM4T(vbh, vd); \
            MMA_F16(acc[2 * ng + 0], ph[k2], vbh[0], vbh[1]); \
            MMA_F16(acc[2 * ng + 1], ph[k2], vbh[2], vbh[3]); \
        } \
    } \
} while (0)

    // pair pipeline: one barrier per 2 key-tiles, 6 buffers
    FISSUE(0); FISSUE(1); FISSUE(2); FISSUE(3);
    for (int kt = 0; kt < FITERS; kt += 2) {
        if (kt < FITERS - 2) { CP_WAIT(2); } else { CP_WAIT(0); }
        __syncthreads();
        if (kt + 4 < FITERS) FISSUE(kt + 4);
        if (kt + 5 < FITERS) FISSUE(kt + 5);
        FBODY(kt);
        FBODY(kt + 1);
    }

    float inv0 = 1.0f / l0, inv1 = 1.0f / l1;
    const int r0g = b * SEQ + q0 + wq * 16 + (lane >> 2);
#pragma unroll
    for (int nt = 0; nt < 16; nt++) {
        int cc = (int)hoff + nt * 8 + ((lane & 3) << 1);
        *(uint32_t*)(Ohi + (size_t)r0g * DIM + cc) =
            pack_h2(acc[nt][0] * inv0, acc[nt][1] * inv0);
        *(uint32_t*)(Ohi + (size_t)(r0g + 8) * DIM + cc) =
            pack_h2(acc[nt][2] * inv1, acc[nt][3] * inv1);
    }
#undef FISSUE
#undef FBODY
}

// ---------------------------------------------------------------------------
extern "C" void kernel_launch(void* const* d_in, const int* in_sizes, int n_in,
                              void* d_out, int out_size)
{
    (void)in_sizes; (void)n_in; (void)out_size;
    const float* x     = (const float*)d_in[0];
    const float* ctx   = (const float*)d_in[1];
    const float* cosb  = (const float*)d_in[2];
    const float* sinb  = (const float*)d_in[3];
    const float* bq    = (const float*)d_in[5];
    const float* bk    = (const float*)d_in[7];
    const float* bv    = (const float*)d_in[9];
    const float* bqc   = (const float*)d_in[11];
    const float* bkc   = (const float*)d_in[13];
    const float* bvc   = (const float*)d_in[15];
    const float* b_out = (const float*)d_in[17];
    const float* b_add = (const float*)d_in[19];
    const float* g_q   = (const float*)d_in[20];
    const float* g_k   = (const float*)d_in[21];
    const float* g_qc  = (const float*)d_in[22];
    const float* g_kc  = (const float*)d_in[23];
    float* out = (float*)d_out;

    __half *Whi, *Xhi, *Qhi, *Khi, *Vhi;
    cudaGetSymbolAddress((void**)&Whi, g_Whi);
    cudaGetSymbolAddress((void**)&Xhi, g_Xhi);
    cudaGetSymbolAddress((void**)&Qhi, g_Qhi);
    cudaGetSymbolAddress((void**)&Khi, g_Khi);
    cudaGetSymbolAddress((void**)&Vhi, g_Vhi);

    cudaFuncSetAttribute(mma_gemm_kernel,
                         cudaFuncAttributeMaxDynamicSharedMemorySize, GEMM_SMEM_BYTES);
    cudaFuncSetAttribute(flash_mma_kernel,
                         cudaFuncAttributeMaxDynamicSharedMemorySize, FLASH_SMEM_BYTES);

    const int WN4 = DIM * DIM / 4;

    // convert all 8 weights to fp16 hi (one launch)
    conv_w8_kernel<<<dim3((WN4 + 255) / 256, 8), 256>>>(
        (const float4*)d_in[4],  (const float4*)d_in[6],  (const float4*)d_in[8],
        (const float4*)d_in[10], (const float4*)d_in[12], (const float4*)d_in[14],
        (const float4*)d_in[16], (const float4*)d_in[18],
        (uint2*)Whi, WN4);

    // activations -> fp16 hi, joint layout
    conv_hi_kernel<<<(BB * S_TXT * (DIM / 4) + 255) / 256, 256>>>(
        (const float4*)ctx, (uint2*)Xhi, S_TXT, 0);
    conv_hi_kernel<<<(BB * S_IMG * (DIM / 4) + 255) / 256, 256>>>(
        (const float4*)x, (uint2*)Xhi, S_IMG, S_TXT);

    // QKV projections: ONE launch, 128-thread CTAs
    dim3 gQKV(DIM / 128, (BB * SEQ) / 128, 3);
    mma_gemm_kernel<<<gQKV, 128, GEMM_SMEM_BYTES>>>(0, Xhi, Whi,
        bq, bk, bv, bqc, bkc, bvc, b_out, b_add,
        g_q, g_k, g_qc, g_kc, cosb, sinb,
        Qhi, Khi, Vhi, nullptr);

    // Flash attention (pure fp16; writes hi output into Xhi)
    flash_mma_kernel<<<dim3(SEQ / 128, BB * HEADS), 256, FLASH_SMEM_BYTES>>>(
        Qhi, Khi, Vhi, Xhi);

    // output projections: ONE launch
    dim3 gOut(DIM / 128, (BB * SEQ) / 128, 1);
    mma_gemm_kernel<<<gOut, 128, GEMM_SMEM_BYTES>>>(1, Xhi, Whi,
        bq, bk, bv, bqc, bkc, bvc, b_out, b_add,
        g_q, g_k, g_qc, g_kc, cosb, sinb,
        Qhi, Khi, Vhi, out);
}